// round 15
// baseline (speedup 1.0000x reference)
#include <cuda_runtime.h>
#include <cuda_bf16.h>
#include <math.h>
#include <stdint.h>

#define Dv   512
#define Nn   8192
#define K1   2560    // 5*D  (Agg_0..3, x)
#define QK   2048    // 4*D  (q,k,v,skip)
#define Tt   256     // tokens per dialog
#define NB   32      // nodes per graph-tile block
#define WROW 48      // max neighbor rows per tile (NB + 8 + 8)

// ---- static scratch (no allocations allowed) ----
__device__ __nv_bfloat16 g_H0[(size_t)Nn * K1];   // 40 MB  [N, 5D] bf16
__device__ __nv_bfloat16 g_ho[(size_t)Nn * Dv];   //  8 MB  [N, D]  bf16
__device__ float         g_qkvs[(size_t)Nn * QK]; // 64 MB  [N, 4, D] fp32
__device__ uint32_t      g_Wp1[(size_t)(K1/2) * Dv];      // packed bf16 [W_rel;W_root]
__device__ uint32_t      g_Wp2[(size_t)4 * (Dv/2) * Dv];  // packed bf16 q|k|v|skip

__device__ __forceinline__ int lower_bound_i(const int* __restrict__ a, int n, int key) {
    int lo = 0, hi = n;
    while (lo < hi) { int m = (lo + hi) >> 1; if (a[m] < key) lo = m + 1; else hi = m; }
    return lo;
}

__device__ __forceinline__ uint32_t packbf(float lo, float hi) {
    __nv_bfloat162 h = __floats2bfloat162_rn(lo, hi);   // x (low) = lo
    return reinterpret_cast<uint32_t&>(h);
}

// m16n8k16 bf16 mma, fp32 accum
__device__ __forceinline__ void mma16(float* d, const uint32_t* a, const uint32_t* b) {
    asm volatile(
        "mma.sync.aligned.m16n8k16.row.col.f32.bf16.bf16.f32 "
        "{%0,%1,%2,%3}, {%4,%5,%6,%7}, {%8,%9}, {%0,%1,%2,%3};"
        : "+f"(d[0]), "+f"(d[1]), "+f"(d[2]), "+f"(d[3])
        : "r"(a[0]), "r"(a[1]), "r"(a[2]), "r"(a[3]), "r"(b[0]), "r"(b[1]));
}

__device__ __forceinline__ void cpa16(void* smem, const void* g) {
    uint32_t s = (uint32_t)__cvta_generic_to_shared(smem);
    asm volatile("cp.async.ca.shared.global [%0], [%1], 16;" :: "r"(s), "l"(g));
}
#define CP_COMMIT() asm volatile("cp.async.commit_group;")
#define CP_WAIT2()  asm volatile("cp.async.wait_group 2;")

// ============================================================
// Kernel 0: pack weights fp32 -> k-pair-packed bf16 uint32
// ============================================================
__global__ __launch_bounds__(512) void pack_weights(
    const float* __restrict__ Wrel, const float* __restrict__ Wroot,
    const float* __restrict__ Wq, const float* __restrict__ Wk,
    const float* __restrict__ Wv, const float* __restrict__ Ws)
{
    int r = blockIdx.x;
    int n = threadIdx.x;
    if (r < K1 / 2) {
        int kk = 2 * r;
        const float* p0 = (kk < 2048) ? (Wrel + (size_t)kk * Dv) : (Wroot + (size_t)(kk - 2048) * Dv);
        const float* p1 = p0 + Dv;
        g_Wp1[(size_t)r * Dv + n] = packbf(p0[n], p1[n]);
    } else {
        int rp = r - K1 / 2;
        int w = rp >> 8, kp = rp & 255;
        const float* W = (w == 0) ? Wq : (w == 1) ? Wk : (w == 2) ? Wv : Ws;
        const float* p0 = W + (size_t)(2 * kp) * Dv;
        g_Wp2[(size_t)rp * Dv + n] = packbf(p0[n], p0[Dv + n]);
    }
}

// ============================================================
// Kernel 1: windowed-tile aggregation -> H0 [N, 5D] (bf16)
// Block = 32 nodes; x rows [n0-8, n0+40) staged in smem once.
// One warp per 4 nodes; lanes split D (16 floats each).
// ============================================================
#define AGG_SMEM (WROW * Dv * 4)   // 98304 B

__global__ __launch_bounds__(256) void agg_kernel(
    const float* __restrict__ x,
    const int*   __restrict__ src,
    const int*   __restrict__ dst,
    const int*   __restrict__ et,
    int E)
{
    extern __shared__ float xs[];    // [WROW][512]
    int n0 = blockIdx.x * NB;
    int dbase = n0 & ~(Tt - 1);
    int lo = n0 - 8; if (lo < dbase) lo = dbase;
    int hi = n0 + NB + 8; if (hi > dbase + Tt) hi = dbase + Tt;
    int nrows = hi - lo;
    int tid = threadIdx.x;

    for (int idx = tid; idx < nrows * 128; idx += 256) {
        int r = idx >> 7, c = idx & 127;
        ((float4*)xs)[r * 128 + c] = ((const float4*)(x + (size_t)(lo + r) * Dv))[c];
    }
    __syncthreads();

    int w = tid >> 5, lane = tid & 31;
    const unsigned FULL = 0xffffffffu;
    for (int s = 0; s < 4; s++) {
        int i = n0 + w * 4 + s;
        int elo = 0, nE = 0;
        if (lane == 0) {
            elo = lower_bound_i(dst, E, i);
            int ehi = lower_bound_i(dst, E, i + 1);
            nE = ehi - elo; if (nE > 16) nE = 16;
        }
        elo = __shfl_sync(FULL, elo, 0);
        nE  = __shfl_sync(FULL, nE, 0);

        int sE = 0, rE = 0;
        if (lane < nE) {
            sE = src[elo + lane] - lo;
            rE = et[elo + lane];
        }
        int c0 = __popc(__ballot_sync(FULL, lane < nE && rE == 0));
        int c1 = __popc(__ballot_sync(FULL, lane < nE && rE == 1));
        int c2 = __popc(__ballot_sync(FULL, lane < nE && rE == 2));
        int c3 = __popc(__ballot_sync(FULL, lane < nE && rE == 3));

        float a0[16] = {}, a1[16] = {}, a2[16] = {}, a3[16] = {};
        int d0 = lane * 16;
        for (int e = 0; e < nE; e++) {
            int row = __shfl_sync(FULL, sE, e);
            int re  = __shfl_sync(FULL, rE, e);
            const float* xr = xs + row * Dv + d0;
            float* acc = (re == 0) ? a0 : (re == 1) ? a1 : (re == 2) ? a2 : a3;
            #pragma unroll
            for (int j = 0; j < 16; j++) acc[j] += xr[j];
        }
        float i0 = 1.f / fmaxf((float)c0, 1.f);
        float i1 = 1.f / fmaxf((float)c1, 1.f);
        float i2 = 1.f / fmaxf((float)c2, 1.f);
        float i3 = 1.f / fmaxf((float)c3, 1.f);
        __nv_bfloat16* H = g_H0 + (size_t)i * K1;
        uint32_t o[8];
        #pragma unroll
        for (int j = 0; j < 8; j++) o[j] = packbf(a0[2*j] * i0, a0[2*j+1] * i0);
        ((uint4*)(H + 0*Dv + d0))[0] = ((uint4*)o)[0];
        ((uint4*)(H + 0*Dv + d0))[1] = ((uint4*)o)[1];
        #pragma unroll
        for (int j = 0; j < 8; j++) o[j] = packbf(a1[2*j] * i1, a1[2*j+1] * i1);
        ((uint4*)(H + 1*Dv + d0))[0] = ((uint4*)o)[0];
        ((uint4*)(H + 1*Dv + d0))[1] = ((uint4*)o)[1];
        #pragma unroll
        for (int j = 0; j < 8; j++) o[j] = packbf(a2[2*j] * i2, a2[2*j+1] * i2);
        ((uint4*)(H + 2*Dv + d0))[0] = ((uint4*)o)[0];
        ((uint4*)(H + 2*Dv + d0))[1] = ((uint4*)o)[1];
        #pragma unroll
        for (int j = 0; j < 8; j++) o[j] = packbf(a3[2*j] * i3, a3[2*j+1] * i3);
        ((uint4*)(H + 3*Dv + d0))[0] = ((uint4*)o)[0];
        ((uint4*)(H + 3*Dv + d0))[1] = ((uint4*)o)[1];
        const float* xr = xs + (i - lo) * Dv + d0;
        #pragma unroll
        for (int j = 0; j < 8; j++) o[j] = packbf(xr[2*j], xr[2*j+1]);
        ((uint4*)(H + 4*Dv + d0))[0] = ((uint4*)o)[0];
        ((uint4*)(H + 4*Dv + d0))[1] = ((uint4*)o)[1];
    }
}

// ============================================================
// bf16 GEMM: 128x128x32 tiles, 8 warps (2x4), warp tile 64x32,
// 4-stage cp.async ring (wait_group 2), dynamic smem.  (R12 proven)
// ============================================================
#define LDA32 20
#define LDB32 136
#define AS_ST (128 * LDA32)
#define BS_ST (16 * LDB32)
#define NSTAGE 4
#define GEMM_SMEM_BYTES ((AS_ST + BS_ST) * NSTAGE * 4)   // 75776

__global__ __launch_bounds__(256) void gemm_rgcn(const float* __restrict__ bias)
{
    extern __shared__ uint32_t smem[];
    uint32_t* As = smem;
    uint32_t* Bs = smem + NSTAGE * AS_ST;
    const __nv_bfloat16* A = g_H0;
    const uint32_t* Wp = g_Wp1;
    __nv_bfloat16* C = g_ho;
    const int K = K1;
    int tid = threadIdx.x;
    int n0 = blockIdx.x * 128, m0 = blockIdx.y * 128;
    int wid = tid >> 5, lane = tid & 31;
    int wr = wid >> 2, wc = wid & 3;
    int g = lane >> 2, tig = lane & 3;
    float acc[4][4][4] = {};

    int a_row0 = tid >> 2,            a_kw0 = (tid & 3) * 4;
    int a_row1 = (tid + 256) >> 2,    a_kw1 = a_kw0;
    int b_kp0  = tid >> 5,            b_n0w = (tid & 31) * 4;
    int b_kp1  = (tid + 256) >> 5,    b_n1w = b_n0w;

    const int ITER = K / 32;   // 80
    #pragma unroll
    for (int s = 0; s < NSTAGE - 1; s++) {
        int kb = s * 32, kpb = s * 16;
        cpa16(&As[s*AS_ST + a_row0 * LDA32 + a_kw0], A + (size_t)(m0 + a_row0) * K + kb + a_kw0 * 2);
        cpa16(&As[s*AS_ST + a_row1 * LDA32 + a_kw1], A + (size_t)(m0 + a_row1) * K + kb + a_kw1 * 2);
        cpa16(&Bs[s*BS_ST + b_kp0 * LDB32 + b_n0w], Wp + (size_t)(kpb + b_kp0) * Dv + n0 + b_n0w);
        cpa16(&Bs[s*BS_ST + b_kp1 * LDB32 + b_n1w], Wp + (size_t)(kpb + b_kp1) * Dv + n0 + b_n1w);
        CP_COMMIT();
    }
    for (int it = 0; it < ITER; ++it) {
        CP_WAIT2();
        __syncthreads();
        if (it + NSTAGE - 1 < ITER) {
            int st = (it + NSTAGE - 1) & (NSTAGE - 1);
            int kb = (it + NSTAGE - 1) * 32;
            int kpb = (it + NSTAGE - 1) * 16;
            cpa16(&As[st*AS_ST + a_row0 * LDA32 + a_kw0], A + (size_t)(m0 + a_row0) * K + kb + a_kw0 * 2);
            cpa16(&As[st*AS_ST + a_row1 * LDA32 + a_kw1], A + (size_t)(m0 + a_row1) * K + kb + a_kw1 * 2);
            cpa16(&Bs[st*BS_ST + b_kp0 * LDB32 + b_n0w], Wp + (size_t)(kpb + b_kp0) * Dv + n0 + b_n0w);
            cpa16(&Bs[st*BS_ST + b_kp1 * LDB32 + b_n1w], Wp + (size_t)(kpb + b_kp1) * Dv + n0 + b_n1w);
        }
        CP_COMMIT();
        const uint32_t* as = &As[(it & (NSTAGE - 1)) * AS_ST];
        const uint32_t* bs = &Bs[(it & (NSTAGE - 1)) * BS_ST];
        #pragma unroll
        for (int ks = 0; ks < 2; ks++) {
            uint32_t af[4][4], bf[4][2];
            #pragma unroll
            for (int mt = 0; mt < 4; mt++) {
                int mr = wr * 64 + mt * 16;
                af[mt][0] = as[(mr + g)     * LDA32 + ks * 8 + tig];
                af[mt][1] = as[(mr + g + 8) * LDA32 + ks * 8 + tig];
                af[mt][2] = as[(mr + g)     * LDA32 + ks * 8 + tig + 4];
                af[mt][3] = as[(mr + g + 8) * LDA32 + ks * 8 + tig + 4];
            }
            #pragma unroll
            for (int nt = 0; nt < 4; nt++) {
                int nc = wc * 32 + nt * 8;
                bf[nt][0] = bs[(ks * 8 + tig)     * LDB32 + nc + g];
                bf[nt][1] = bs[(ks * 8 + tig + 4) * LDB32 + nc + g];
            }
            #pragma unroll
            for (int mt = 0; mt < 4; mt++)
                #pragma unroll
                for (int nt = 0; nt < 4; nt++)
                    mma16(acc[mt][nt], af[mt], bf[nt]);
        }
    }
    #pragma unroll
    for (int mt = 0; mt < 4; mt++) {
        int mr = m0 + wr * 64 + mt * 16;
        #pragma unroll
        for (int nt = 0; nt < 4; nt++) {
            int nc = n0 + wc * 32 + nt * 8 + 2 * tig;
            float b0 = bias[nc], b1 = bias[nc + 1];
            uint32_t v0 = packbf(acc[mt][nt][0] + b0, acc[mt][nt][1] + b1);
            uint32_t v1 = packbf(acc[mt][nt][2] + b0, acc[mt][nt][3] + b1);
            *(uint32_t*)(C + (size_t)(mr + g)     * Dv + nc) = v0;
            *(uint32_t*)(C + (size_t)(mr + g + 8) * Dv + nc) = v1;
        }
    }
}

__global__ __launch_bounds__(256) void gemm_qkvs(
    const float* __restrict__ bq, const float* __restrict__ bk,
    const float* __restrict__ bv, const float* __restrict__ bs_)
{
    extern __shared__ uint32_t smem[];
    uint32_t* As = smem;
    uint32_t* Bs = smem + NSTAGE * AS_ST;
    const __nv_bfloat16* A = g_ho;
    float* C = g_qkvs;
    const int K = Dv;
    int tid = threadIdx.x;
    int n0 = blockIdx.x * 128, m0 = blockIdx.y * 128;
    int wsel = n0 >> 9;
    const uint32_t* Wp = g_Wp2 + (size_t)wsel * (Dv / 2) * Dv;
    const float* bb = (wsel == 0) ? bq : (wsel == 1) ? bk : (wsel == 2) ? bv : bs_;
    int bc0 = n0 & 511;
    int wid = tid >> 5, lane = tid & 31;
    int wr = wid >> 2, wc = wid & 3;
    int g = lane >> 2, tig = lane & 3;
    float acc[4][4][4] = {};

    int a_row0 = tid >> 2,         a_kw0 = (tid & 3) * 4;
    int a_row1 = (tid + 256) >> 2, a_kw1 = a_kw0;
    int b_kp0  = tid >> 5,         b_n0w = (tid & 31) * 4;
    int b_kp1  = (tid + 256) >> 5, b_n1w = b_n0w;

    const int ITER = K / 32;   // 16
    #pragma unroll
    for (int s = 0; s < NSTAGE - 1; s++) {
        int kb = s * 32, kpb = s * 16;
        cpa16(&As[s*AS_ST + a_row0 * LDA32 + a_kw0], A + (size_t)(m0 + a_row0) * K + kb + a_kw0 * 2);
        cpa16(&As[s*AS_ST + a_row1 * LDA32 + a_kw1], A + (size_t)(m0 + a_row1) * K + kb + a_kw1 * 2);
        cpa16(&Bs[s*BS_ST + b_kp0 * LDB32 + b_n0w], Wp + (size_t)(kpb + b_kp0) * Dv + bc0 + b_n0w);
        cpa16(&Bs[s*BS_ST + b_kp1 * LDB32 + b_n1w], Wp + (size_t)(kpb + b_kp1) * Dv + bc0 + b_n1w);
        CP_COMMIT();
    }
    for (int it = 0; it < ITER; ++it) {
        CP_WAIT2();
        __syncthreads();
        if (it + NSTAGE - 1 < ITER) {
            int st = (it + NSTAGE - 1) & (NSTAGE - 1);
            int kb = (it + NSTAGE - 1) * 32;
            int kpb = (it + NSTAGE - 1) * 16;
            cpa16(&As[st*AS_ST + a_row0 * LDA32 + a_kw0], A + (size_t)(m0 + a_row0) * K + kb + a_kw0 * 2);
            cpa16(&As[st*AS_ST + a_row1 * LDA32 + a_kw1], A + (size_t)(m0 + a_row1) * K + kb + a_kw1 * 2);
            cpa16(&Bs[st*BS_ST + b_kp0 * LDB32 + b_n0w], Wp + (size_t)(kpb + b_kp0) * Dv + bc0 + b_n0w);
            cpa16(&Bs[st*BS_ST + b_kp1 * LDB32 + b_n1w], Wp + (size_t)(kpb + b_kp1) * Dv + bc0 + b_n1w);
        }
        CP_COMMIT();
        const uint32_t* as = &As[(it & (NSTAGE - 1)) * AS_ST];
        const uint32_t* bs = &Bs[(it & (NSTAGE - 1)) * BS_ST];
        #pragma unroll
        for (int ks = 0; ks < 2; ks++) {
            uint32_t af[4][4], bf[4][2];
            #pragma unroll
            for (int mt = 0; mt < 4; mt++) {
                int mr = wr * 64 + mt * 16;
                af[mt][0] = as[(mr + g)     * LDA32 + ks * 8 + tig];
                af[mt][1] = as[(mr + g + 8) * LDA32 + ks * 8 + tig];
                af[mt][2] = as[(mr + g)     * LDA32 + ks * 8 + tig + 4];
                af[mt][3] = as[(mr + g + 8) * LDA32 + ks * 8 + tig + 4];
            }
            #pragma unroll
            for (int nt = 0; nt < 4; nt++) {
                int nc = wc * 32 + nt * 8;
                bf[nt][0] = bs[(ks * 8 + tig)     * LDB32 + nc + g];
                bf[nt][1] = bs[(ks * 8 + tig + 4) * LDB32 + nc + g];
            }
            #pragma unroll
            for (int mt = 0; mt < 4; mt++)
                #pragma unroll
                for (int nt = 0; nt < 4; nt++)
                    mma16(acc[mt][nt], af[mt], bf[nt]);
        }
    }
    #pragma unroll
    for (int mt = 0; mt < 4; mt++) {
        int mr = m0 + wr * 64 + mt * 16;
        #pragma unroll
        for (int nt = 0; nt < 4; nt++) {
            int colw = wc * 32 + nt * 8 + 2 * tig;
            int nc = n0 + colw;
            int bi = bc0 + colw;
            float b0 = bb[bi], b1 = bb[bi + 1];
            float2 v0 = {acc[mt][nt][0] + b0, acc[mt][nt][1] + b1};
            float2 v1 = {acc[mt][nt][2] + b0, acc[mt][nt][3] + b1};
            *(float2*)(C + (size_t)(mr + g)     * QK + nc) = v0;
            *(float2*)(C + (size_t)(mr + g + 8) * QK + nc) = v1;
        }
    }
}

// ============================================================
// Kernel 4: windowed-tile attention + skip + leaky + residual + LN
// Block = 32 nodes; k,v rows [n0-8, n0+40) staged in smem.
// One warp per 4 nodes; lanes split D (16 floats each).
// ============================================================
#define ATT_SMEM ((2 * WROW * Dv + 2 * Dv) * 4)   // 200704 B

__global__ __launch_bounds__(256) void attn_kernel(
    const float* __restrict__ x,
    const int*   __restrict__ src,
    const int*   __restrict__ dst,
    int E,
    const float* __restrict__ gamma,
    const float* __restrict__ beta,
    float* __restrict__ out)
{
    extern __shared__ float sm[];
    float* ks = sm;                  // [WROW][512]
    float* vs = sm + WROW * Dv;      // [WROW][512]
    float* gm = vs + WROW * Dv;      // [512]
    float* bt = gm + Dv;             // [512]
    const float* qkvs = g_qkvs;

    int n0 = blockIdx.x * NB;
    int dbase = n0 & ~(Tt - 1);
    int lo = n0 - 8; if (lo < dbase) lo = dbase;
    int hi = n0 + NB + 8; if (hi > dbase + Tt) hi = dbase + Tt;
    int nrows = hi - lo;
    int tid = threadIdx.x;

    for (int idx = tid; idx < 128; idx += 256) {
        ((float4*)gm)[idx] = ((const float4*)gamma)[idx];
        ((float4*)bt)[idx] = ((const float4*)beta)[idx];
    }
    for (int idx = tid; idx < nrows * 128; idx += 256) {
        int r = idx >> 7, c = idx & 127;
        const float* row = qkvs + (size_t)(lo + r) * QK;
        ((float4*)ks)[r * 128 + c] = ((const float4*)(row + 512))[c];
        ((float4*)vs)[r * 128 + c] = ((const float4*)(row + 1024))[c];
    }
    __syncthreads();

    int w = tid >> 5, lane = tid & 31;
    const unsigned FULL = 0xffffffffu;
    const float scale = 0.04419417382415922f;   // 1/sqrt(512)

    for (int s = 0; s < 4; s++) {
        int i = n0 + w * 4 + s;
        int elo = 0, nE = 0;
        if (lane == 0) {
            elo = lower_bound_i(dst, E, i);
            int ehi = lower_bound_i(dst, E, i + 1);
            nE = ehi - elo; if (nE > 16) nE = 16;
        }
        elo = __shfl_sync(FULL, elo, 0);
        nE  = __shfl_sync(FULL, nE, 0);

        int sE = 0;
        if (lane < nE) sE = src[elo + lane] - lo;

        int d0 = lane * 16;
        float4 q[4];
        const float* qp = qkvs + (size_t)i * QK + d0;
        #pragma unroll
        for (int j = 0; j < 4; j++) q[j] = ((const float4*)qp)[j];

        // logits: lane e holds logit of edge e
        float lg = -INFINITY;
        for (int e = 0; e < nE; e++) {
            int row = __shfl_sync(FULL, sE, e);
            const float4* kr = (const float4*)(ks + row * Dv + d0);
            float sum = 0.f;
            #pragma unroll
            for (int j = 0; j < 4; j++) {
                float4 kb = kr[j];
                sum += q[j].x*kb.x + q[j].y*kb.y + q[j].z*kb.z + q[j].w*kb.w;
            }
            #pragma unroll
            for (int o = 16; o; o >>= 1) sum += __shfl_xor_sync(FULL, sum, o);
            if (lane == e) lg = sum * scale;
        }
        float mx = lg;
        #pragma unroll
        for (int o = 16; o; o >>= 1) mx = fmaxf(mx, __shfl_xor_sync(FULL, mx, o));
        if (!isfinite(mx)) mx = 0.f;
        float ex = (lane < nE) ? expf(lg - mx) : 0.f;
        float den = ex;
        #pragma unroll
        for (int o = 16; o; o >>= 1) den += __shfl_xor_sync(FULL, den, o);
        float inv = 1.f / fmaxf(den, 1e-16f);

        float acc[16] = {};
        for (int e = 0; e < nE; e++) {
            int row = __shfl_sync(FULL, sE, e);
            float a = __shfl_sync(FULL, ex, e) * inv;
            const float4* vr = (const float4*)(vs + row * Dv + d0);
            #pragma unroll
            for (int j = 0; j < 4; j++) {
                float4 vv = vr[j];
                acc[4*j+0] += a * vv.x; acc[4*j+1] += a * vv.y;
                acc[4*j+2] += a * vv.z; acc[4*j+3] += a * vv.w;
            }
        }

        const float4* skp = (const float4*)(qkvs + (size_t)i * QK + 1536 + d0);
        const float4* xp  = (const float4*)(x + (size_t)i * Dv + d0);
        float o16[16];
        float s1 = 0.f, s2 = 0.f;
        #pragma unroll
        for (int j = 0; j < 4; j++) {
            float4 sk = skp[j];
            float4 xv = xp[j];
            float h0 = acc[4*j+0] + sk.x, h1 = acc[4*j+1] + sk.y;
            float h2 = acc[4*j+2] + sk.z, h3 = acc[4*j+3] + sk.w;
            h0 = h0 > 0.f ? h0 : 0.01f * h0;
            h1 = h1 > 0.f ? h1 : 0.01f * h1;
            h2 = h2 > 0.f ? h2 : 0.01f * h2;
            h3 = h3 > 0.f ? h3 : 0.01f * h3;
            float o0 = xv.x + h0, o1 = xv.y + h1, o2 = xv.z + h2, o3 = xv.w + h3;
            o16[4*j+0] = o0; o16[4*j+1] = o1; o16[4*j+2] = o2; o16[4*j+3] = o3;
            s1 += o0 + o1 + o2 + o3;
            s2 += o0*o0 + o1*o1 + o2*o2 + o3*o3;
        }
        #pragma unroll
        for (int o = 16; o; o >>= 1) {
            s1 += __shfl_xor_sync(FULL, s1, o);
            s2 += __shfl_xor_sync(FULL, s2, o);
        }
        float mu = s1 / 512.f;
        float var = s2 / 512.f - mu * mu;
        float rs = rsqrtf(var + 1e-5f);

        float4* op = (float4*)(out + (size_t)i * Dv + d0);
        #pragma unroll
        for (int j = 0; j < 4; j++) {
            float4 gj = ((const float4*)(gm + d0))[j];
            float4 bj = ((const float4*)(bt + d0))[j];
            float4 ov;
            ov.x = (o16[4*j+0] - mu) * rs * gj.x + bj.x;
            ov.y = (o16[4*j+1] - mu) * rs * gj.y + bj.y;
            ov.z = (o16[4*j+2] - mu) * rs * gj.z + bj.z;
            ov.w = (o16[4*j+3] - mu) * rs * gj.w + bj.w;
            op[j] = ov;
        }
    }
}

// scalar loss output (always 0 in eval path)
__global__ void tail_kernel(float* out, int out_size) {
    int idx = Nn * Dv + threadIdx.x;
    if (idx < out_size) out[idx] = 0.f;
}

extern "C" void kernel_launch(void* const* d_in, const int* in_sizes, int n_in,
                              void* d_out, int out_size) {
    const float* x     = (const float*)d_in[0];
    const int*   ei    = (const int*)  d_in[1];
    const int*   et    = (const int*)  d_in[2];
    const float* Wrel  = (const float*)d_in[3];
    const float* Wroot = (const float*)d_in[4];
    const float* brg   = (const float*)d_in[5];
    const float* Wq    = (const float*)d_in[6];
    const float* bq    = (const float*)d_in[7];
    const float* Wk    = (const float*)d_in[8];
    const float* bk    = (const float*)d_in[9];
    const float* Wv    = (const float*)d_in[10];
    const float* bv    = (const float*)d_in[11];
    const float* Wsk   = (const float*)d_in[12];
    const float* bsk   = (const float*)d_in[13];
    const float* gamma = (const float*)d_in[14];
    const float* beta  = (const float*)d_in[15];
    float* out = (float*)d_out;

    int E = in_sizes[2];
    const int* src = ei;
    const int* dst = ei + E;

    cudaFuncSetAttribute(gemm_rgcn, cudaFuncAttributeMaxDynamicSharedMemorySize, GEMM_SMEM_BYTES);
    cudaFuncSetAttribute(gemm_qkvs, cudaFuncAttributeMaxDynamicSharedMemorySize, GEMM_SMEM_BYTES);
    cudaFuncSetAttribute(agg_kernel, cudaFuncAttributeMaxDynamicSharedMemorySize, AGG_SMEM);
    cudaFuncSetAttribute(attn_kernel, cudaFuncAttributeMaxDynamicSharedMemorySize, ATT_SMEM);

    pack_weights<<<K1 / 2 + 4 * (Dv / 2), 512>>>(Wrel, Wroot, Wq, Wk, Wv, Wsk);
    agg_kernel<<<Nn / NB, 256, AGG_SMEM>>>(x, src, dst, et, E);
    gemm_rgcn<<<dim3(Dv / 128, Nn / 128), 256, GEMM_SMEM_BYTES>>>(brg);
    gemm_qkvs<<<dim3(QK / 128, Nn / 128), 256, GEMM_SMEM_BYTES>>>(bq, bk, bv, bsk);
    attn_kernel<<<Nn / NB, 256, ATT_SMEM>>>(x, src, dst, E, gamma, beta, out);
    if (out_size > Nn * Dv) tail_kernel<<<1, 256>>>(out, out_size);
}

// round 16
// speedup vs baseline: 1.2435x; 1.2435x over previous
#include <cuda_runtime.h>
#include <cuda_bf16.h>
#include <math.h>
#include <stdint.h>

#define Dv   512
#define Nn   8192
#define K1   2560    // 5*D  (Agg_0..3, x)
#define QK   2048    // 4*D  (q,k,v,skip)
#define Tt   256     // tokens per dialog
#define NB   32      // nodes per graph-tile block
#define WROW 48      // max neighbor rows per tile (NB + 8 + 8)

// ---- static scratch (no allocations allowed) ----
__device__ __nv_bfloat16 g_H0[(size_t)Nn * K1];   // 40 MB  [N, 5D] bf16
__device__ __nv_bfloat16 g_ho[(size_t)Nn * Dv];   //  8 MB  [N, D]  bf16
__device__ float         g_qkvs[(size_t)Nn * QK]; // 64 MB  [N, 4, D] fp32
__device__ uint32_t      g_Wp1[(size_t)(K1/2) * Dv];      // packed bf16 [W_rel;W_root]
__device__ uint32_t      g_Wp2[(size_t)4 * (Dv/2) * Dv];  // packed bf16 q|k|v|skip

__device__ __forceinline__ int lower_bound_i(const int* __restrict__ a, int n, int key) {
    int lo = 0, hi = n;
    while (lo < hi) { int m = (lo + hi) >> 1; if (a[m] < key) lo = m + 1; else hi = m; }
    return lo;
}

__device__ __forceinline__ uint32_t packbf(float lo, float hi) {
    __nv_bfloat162 h = __floats2bfloat162_rn(lo, hi);   // x (low) = lo
    return reinterpret_cast<uint32_t&>(h);
}

// m16n8k16 bf16 mma, fp32 accum
__device__ __forceinline__ void mma16(float* d, const uint32_t* a, const uint32_t* b) {
    asm volatile(
        "mma.sync.aligned.m16n8k16.row.col.f32.bf16.bf16.f32 "
        "{%0,%1,%2,%3}, {%4,%5,%6,%7}, {%8,%9}, {%0,%1,%2,%3};"
        : "+f"(d[0]), "+f"(d[1]), "+f"(d[2]), "+f"(d[3])
        : "r"(a[0]), "r"(a[1]), "r"(a[2]), "r"(a[3]), "r"(b[0]), "r"(b[1]));
}

__device__ __forceinline__ void cpa16(void* smem, const void* g) {
    uint32_t s = (uint32_t)__cvta_generic_to_shared(smem);
    asm volatile("cp.async.ca.shared.global [%0], [%1], 16;" :: "r"(s), "l"(g));
}
#define CP_COMMIT() asm volatile("cp.async.commit_group;")
#define CP_WAIT2()  asm volatile("cp.async.wait_group 2;")

// ============================================================
// Kernel 0: pack weights fp32 -> k-pair-packed bf16 uint32
// ============================================================
__global__ __launch_bounds__(512) void pack_weights(
    const float* __restrict__ Wrel, const float* __restrict__ Wroot,
    const float* __restrict__ Wq, const float* __restrict__ Wk,
    const float* __restrict__ Wv, const float* __restrict__ Ws)
{
    int r = blockIdx.x;
    int n = threadIdx.x;
    if (r < K1 / 2) {
        int kk = 2 * r;
        const float* p0 = (kk < 2048) ? (Wrel + (size_t)kk * Dv) : (Wroot + (size_t)(kk - 2048) * Dv);
        const float* p1 = p0 + Dv;
        g_Wp1[(size_t)r * Dv + n] = packbf(p0[n], p1[n]);
    } else {
        int rp = r - K1 / 2;
        int w = rp >> 8, kp = rp & 255;
        const float* W = (w == 0) ? Wq : (w == 1) ? Wk : (w == 2) ? Wv : Ws;
        const float* p0 = W + (size_t)(2 * kp) * Dv;
        g_Wp2[(size_t)rp * Dv + n] = packbf(p0[n], p0[Dv + n]);
    }
}

// ============================================================
// Kernel 1: windowed-tile aggregation -> H0 [N, 5D] (bf16)
// Block = 32 nodes; x rows [n0-8, n0+40) staged in smem once.
// One warp per 4 nodes; lane covers float4s at lane*4 + c*128
// (conflict-free: each 8-lane LDS.128 phase spans 128 contiguous B).
// ============================================================
#define AGG_SMEM (WROW * Dv * 4)   // 98304 B

__global__ __launch_bounds__(256) void agg_kernel(
    const float* __restrict__ x,
    const int*   __restrict__ src,
    const int*   __restrict__ dst,
    const int*   __restrict__ et,
    int E)
{
    extern __shared__ float xs[];    // [WROW][512]
    int n0 = blockIdx.x * NB;
    int dbase = n0 & ~(Tt - 1);
    int lo = n0 - 8; if (lo < dbase) lo = dbase;
    int hi = n0 + NB + 8; if (hi > dbase + Tt) hi = dbase + Tt;
    int nrows = hi - lo;
    int tid = threadIdx.x;

    for (int idx = tid; idx < nrows * 128; idx += 256) {
        int r = idx >> 7, c = idx & 127;
        ((float4*)xs)[r * 128 + c] = ((const float4*)(x + (size_t)(lo + r) * Dv))[c];
    }
    __syncthreads();

    int w = tid >> 5, lane = tid & 31;
    const unsigned FULL = 0xffffffffu;
    for (int s = 0; s < 4; s++) {
        int i = n0 + w * 4 + s;
        int elo = 0, nE = 0;
        if (lane == 0) {
            elo = lower_bound_i(dst, E, i);
            int ehi = lower_bound_i(dst, E, i + 1);
            nE = ehi - elo; if (nE > 16) nE = 16;
        }
        elo = __shfl_sync(FULL, elo, 0);
        nE  = __shfl_sync(FULL, nE, 0);

        int sE = 0, rE = 0;
        if (lane < nE) {
            sE = src[elo + lane] - lo;
            rE = et[elo + lane];
        }
        int c0 = __popc(__ballot_sync(FULL, lane < nE && rE == 0));
        int c1 = __popc(__ballot_sync(FULL, lane < nE && rE == 1));
        int c2 = __popc(__ballot_sync(FULL, lane < nE && rE == 2));
        int c3 = __popc(__ballot_sync(FULL, lane < nE && rE == 3));

        float4 a0[4] = {}, a1[4] = {}, a2[4] = {}, a3[4] = {};
        for (int e = 0; e < nE; e++) {
            int row = __shfl_sync(FULL, sE, e);
            int re  = __shfl_sync(FULL, rE, e);
            const float4* xr = (const float4*)(xs + row * Dv) + lane;
            float4* acc = (re == 0) ? a0 : (re == 1) ? a1 : (re == 2) ? a2 : a3;
            #pragma unroll
            for (int c = 0; c < 4; c++) {
                float4 v = xr[c * 32];
                acc[c].x += v.x; acc[c].y += v.y; acc[c].z += v.z; acc[c].w += v.w;
            }
        }
        float i0 = 1.f / fmaxf((float)c0, 1.f);
        float i1 = 1.f / fmaxf((float)c1, 1.f);
        float i2 = 1.f / fmaxf((float)c2, 1.f);
        float i3 = 1.f / fmaxf((float)c3, 1.f);
        __nv_bfloat16* H = g_H0 + (size_t)i * K1;
        #pragma unroll
        for (int c = 0; c < 4; c++) {
            uint2 o;
            o.x = packbf(a0[c].x * i0, a0[c].y * i0);
            o.y = packbf(a0[c].z * i0, a0[c].w * i0);
            *(uint2*)(H + 0*Dv + c * 128 + lane * 4) = o;
            o.x = packbf(a1[c].x * i1, a1[c].y * i1);
            o.y = packbf(a1[c].z * i1, a1[c].w * i1);
            *(uint2*)(H + 1*Dv + c * 128 + lane * 4) = o;
            o.x = packbf(a2[c].x * i2, a2[c].y * i2);
            o.y = packbf(a2[c].z * i2, a2[c].w * i2);
            *(uint2*)(H + 2*Dv + c * 128 + lane * 4) = o;
            o.x = packbf(a3[c].x * i3, a3[c].y * i3);
            o.y = packbf(a3[c].z * i3, a3[c].w * i3);
            *(uint2*)(H + 3*Dv + c * 128 + lane * 4) = o;
        }
        const float4* xr = (const float4*)(xs + (i - lo) * Dv) + lane;
        #pragma unroll
        for (int c = 0; c < 4; c++) {
            float4 v = xr[c * 32];
            uint2 o;
            o.x = packbf(v.x, v.y);
            o.y = packbf(v.z, v.w);
            *(uint2*)(H + 4*Dv + c * 128 + lane * 4) = o;
        }
    }
}

// ============================================================
// bf16 GEMM: 128x128x32 tiles, 8 warps (2x4), warp tile 64x32,
// 4-stage cp.async ring (wait_group 2), dynamic smem.  (R12 proven)
// ============================================================
#define LDA32 20
#define LDB32 136
#define AS_ST (128 * LDA32)
#define BS_ST (16 * LDB32)
#define NSTAGE 4
#define GEMM_SMEM_BYTES ((AS_ST + BS_ST) * NSTAGE * 4)   // 75776

__global__ __launch_bounds__(256) void gemm_rgcn(const float* __restrict__ bias)
{
    extern __shared__ uint32_t smem[];
    uint32_t* As = smem;
    uint32_t* Bs = smem + NSTAGE * AS_ST;
    const __nv_bfloat16* A = g_H0;
    const uint32_t* Wp = g_Wp1;
    __nv_bfloat16* C = g_ho;
    const int K = K1;
    int tid = threadIdx.x;
    int n0 = blockIdx.x * 128, m0 = blockIdx.y * 128;
    int wid = tid >> 5, lane = tid & 31;
    int wr = wid >> 2, wc = wid & 3;
    int g = lane >> 2, tig = lane & 3;
    float acc[4][4][4] = {};

    int a_row0 = tid >> 2,            a_kw0 = (tid & 3) * 4;
    int a_row1 = (tid + 256) >> 2,    a_kw1 = a_kw0;
    int b_kp0  = tid >> 5,            b_n0w = (tid & 31) * 4;
    int b_kp1  = (tid + 256) >> 5,    b_n1w = b_n0w;

    const int ITER = K / 32;   // 80
    #pragma unroll
    for (int s = 0; s < NSTAGE - 1; s++) {
        int kb = s * 32, kpb = s * 16;
        cpa16(&As[s*AS_ST + a_row0 * LDA32 + a_kw0], A + (size_t)(m0 + a_row0) * K + kb + a_kw0 * 2);
        cpa16(&As[s*AS_ST + a_row1 * LDA32 + a_kw1], A + (size_t)(m0 + a_row1) * K + kb + a_kw1 * 2);
        cpa16(&Bs[s*BS_ST + b_kp0 * LDB32 + b_n0w], Wp + (size_t)(kpb + b_kp0) * Dv + n0 + b_n0w);
        cpa16(&Bs[s*BS_ST + b_kp1 * LDB32 + b_n1w], Wp + (size_t)(kpb + b_kp1) * Dv + n0 + b_n1w);
        CP_COMMIT();
    }
    for (int it = 0; it < ITER; ++it) {
        CP_WAIT2();
        __syncthreads();
        if (it + NSTAGE - 1 < ITER) {
            int st = (it + NSTAGE - 1) & (NSTAGE - 1);
            int kb = (it + NSTAGE - 1) * 32;
            int kpb = (it + NSTAGE - 1) * 16;
            cpa16(&As[st*AS_ST + a_row0 * LDA32 + a_kw0], A + (size_t)(m0 + a_row0) * K + kb + a_kw0 * 2);
            cpa16(&As[st*AS_ST + a_row1 * LDA32 + a_kw1], A + (size_t)(m0 + a_row1) * K + kb + a_kw1 * 2);
            cpa16(&Bs[st*BS_ST + b_kp0 * LDB32 + b_n0w], Wp + (size_t)(kpb + b_kp0) * Dv + n0 + b_n0w);
            cpa16(&Bs[st*BS_ST + b_kp1 * LDB32 + b_n1w], Wp + (size_t)(kpb + b_kp1) * Dv + n0 + b_n1w);
        }
        CP_COMMIT();
        const uint32_t* as = &As[(it & (NSTAGE - 1)) * AS_ST];
        const uint32_t* bs = &Bs[(it & (NSTAGE - 1)) * BS_ST];
        #pragma unroll
        for (int ks = 0; ks < 2; ks++) {
            uint32_t af[4][4], bf[4][2];
            #pragma unroll
            for (int mt = 0; mt < 4; mt++) {
                int mr = wr * 64 + mt * 16;
                af[mt][0] = as[(mr + g)     * LDA32 + ks * 8 + tig];
                af[mt][1] = as[(mr + g + 8) * LDA32 + ks * 8 + tig];
                af[mt][2] = as[(mr + g)     * LDA32 + ks * 8 + tig + 4];
                af[mt][3] = as[(mr + g + 8) * LDA32 + ks * 8 + tig + 4];
            }
            #pragma unroll
            for (int nt = 0; nt < 4; nt++) {
                int nc = wc * 32 + nt * 8;
                bf[nt][0] = bs[(ks * 8 + tig)     * LDB32 + nc + g];
                bf[nt][1] = bs[(ks * 8 + tig + 4) * LDB32 + nc + g];
            }
            #pragma unroll
            for (int mt = 0; mt < 4; mt++)
                #pragma unroll
                for (int nt = 0; nt < 4; nt++)
                    mma16(acc[mt][nt], af[mt], bf[nt]);
        }
    }
    #pragma unroll
    for (int mt = 0; mt < 4; mt++) {
        int mr = m0 + wr * 64 + mt * 16;
        #pragma unroll
        for (int nt = 0; nt < 4; nt++) {
            int nc = n0 + wc * 32 + nt * 8 + 2 * tig;
            float b0 = bias[nc], b1 = bias[nc + 1];
            uint32_t v0 = packbf(acc[mt][nt][0] + b0, acc[mt][nt][1] + b1);
            uint32_t v1 = packbf(acc[mt][nt][2] + b0, acc[mt][nt][3] + b1);
            *(uint32_t*)(C + (size_t)(mr + g)     * Dv + nc) = v0;
            *(uint32_t*)(C + (size_t)(mr + g + 8) * Dv + nc) = v1;
        }
    }
}

__global__ __launch_bounds__(256) void gemm_qkvs(
    const float* __restrict__ bq, const float* __restrict__ bk,
    const float* __restrict__ bv, const float* __restrict__ bs_)
{
    extern __shared__ uint32_t smem[];
    uint32_t* As = smem;
    uint32_t* Bs = smem + NSTAGE * AS_ST;
    const __nv_bfloat16* A = g_ho;
    float* C = g_qkvs;
    const int K = Dv;
    int tid = threadIdx.x;
    int n0 = blockIdx.x * 128, m0 = blockIdx.y * 128;
    int wsel = n0 >> 9;
    const uint32_t* Wp = g_Wp2 + (size_t)wsel * (Dv / 2) * Dv;
    const float* bb = (wsel == 0) ? bq : (wsel == 1) ? bk : (wsel == 2) ? bv : bs_;
    int bc0 = n0 & 511;
    int wid = tid >> 5, lane = tid & 31;
    int wr = wid >> 2, wc = wid & 3;
    int g = lane >> 2, tig = lane & 3;
    float acc[4][4][4] = {};

    int a_row0 = tid >> 2,         a_kw0 = (tid & 3) * 4;
    int a_row1 = (tid + 256) >> 2, a_kw1 = a_kw0;
    int b_kp0  = tid >> 5,         b_n0w = (tid & 31) * 4;
    int b_kp1  = (tid + 256) >> 5, b_n1w = b_n0w;

    const int ITER = K / 32;   // 16
    #pragma unroll
    for (int s = 0; s < NSTAGE - 1; s++) {
        int kb = s * 32, kpb = s * 16;
        cpa16(&As[s*AS_ST + a_row0 * LDA32 + a_kw0], A + (size_t)(m0 + a_row0) * K + kb + a_kw0 * 2);
        cpa16(&As[s*AS_ST + a_row1 * LDA32 + a_kw1], A + (size_t)(m0 + a_row1) * K + kb + a_kw1 * 2);
        cpa16(&Bs[s*BS_ST + b_kp0 * LDB32 + b_n0w], Wp + (size_t)(kpb + b_kp0) * Dv + bc0 + b_n0w);
        cpa16(&Bs[s*BS_ST + b_kp1 * LDB32 + b_n1w], Wp + (size_t)(kpb + b_kp1) * Dv + bc0 + b_n1w);
        CP_COMMIT();
    }
    for (int it = 0; it < ITER; ++it) {
        CP_WAIT2();
        __syncthreads();
        if (it + NSTAGE - 1 < ITER) {
            int st = (it + NSTAGE - 1) & (NSTAGE - 1);
            int kb = (it + NSTAGE - 1) * 32;
            int kpb = (it + NSTAGE - 1) * 16;
            cpa16(&As[st*AS_ST + a_row0 * LDA32 + a_kw0], A + (size_t)(m0 + a_row0) * K + kb + a_kw0 * 2);
            cpa16(&As[st*AS_ST + a_row1 * LDA32 + a_kw1], A + (size_t)(m0 + a_row1) * K + kb + a_kw1 * 2);
            cpa16(&Bs[st*BS_ST + b_kp0 * LDB32 + b_n0w], Wp + (size_t)(kpb + b_kp0) * Dv + bc0 + b_n0w);
            cpa16(&Bs[st*BS_ST + b_kp1 * LDB32 + b_n1w], Wp + (size_t)(kpb + b_kp1) * Dv + bc0 + b_n1w);
        }
        CP_COMMIT();
        const uint32_t* as = &As[(it & (NSTAGE - 1)) * AS_ST];
        const uint32_t* bs = &Bs[(it & (NSTAGE - 1)) * BS_ST];
        #pragma unroll
        for (int ks = 0; ks < 2; ks++) {
            uint32_t af[4][4], bf[4][2];
            #pragma unroll
            for (int mt = 0; mt < 4; mt++) {
                int mr = wr * 64 + mt * 16;
                af[mt][0] = as[(mr + g)     * LDA32 + ks * 8 + tig];
                af[mt][1] = as[(mr + g + 8) * LDA32 + ks * 8 + tig];
                af[mt][2] = as[(mr + g)     * LDA32 + ks * 8 + tig + 4];
                af[mt][3] = as[(mr + g + 8) * LDA32 + ks * 8 + tig + 4];
            }
            #pragma unroll
            for (int nt = 0; nt < 4; nt++) {
                int nc = wc * 32 + nt * 8;
                bf[nt][0] = bs[(ks * 8 + tig)     * LDB32 + nc + g];
                bf[nt][1] = bs[(ks * 8 + tig + 4) * LDB32 + nc + g];
            }
            #pragma unroll
            for (int mt = 0; mt < 4; mt++)
                #pragma unroll
                for (int nt = 0; nt < 4; nt++)
                    mma16(acc[mt][nt], af[mt], bf[nt]);
        }
    }
    #pragma unroll
    for (int mt = 0; mt < 4; mt++) {
        int mr = m0 + wr * 64 + mt * 16;
        #pragma unroll
        for (int nt = 0; nt < 4; nt++) {
            int colw = wc * 32 + nt * 8 + 2 * tig;
            int nc = n0 + colw;
            int bi = bc0 + colw;
            float b0 = bb[bi], b1 = bb[bi + 1];
            float2 v0 = {acc[mt][nt][0] + b0, acc[mt][nt][1] + b1};
            float2 v1 = {acc[mt][nt][2] + b0, acc[mt][nt][3] + b1};
            *(float2*)(C + (size_t)(mr + g)     * QK + nc) = v0;
            *(float2*)(C + (size_t)(mr + g + 8) * QK + nc) = v1;
        }
    }
}

// ============================================================
// Kernel 4: windowed-tile attention + skip + leaky + residual + LN
// Block = 32 nodes; k,v rows staged in smem. Lane covers float4s
// at lane*4 + c*128 (conflict-free LDS.128 phases).
// ============================================================
#define ATT_SMEM ((2 * WROW * Dv + 2 * Dv) * 4)   // 200704 B

__global__ __launch_bounds__(256) void attn_kernel(
    const float* __restrict__ x,
    const int*   __restrict__ src,
    const int*   __restrict__ dst,
    int E,
    const float* __restrict__ gamma,
    const float* __restrict__ beta,
    float* __restrict__ out)
{
    extern __shared__ float sm[];
    float* ks = sm;                  // [WROW][512]
    float* vs = sm + WROW * Dv;      // [WROW][512]
    float* gm = vs + WROW * Dv;      // [512]
    float* bt = gm + Dv;             // [512]
    const float* qkvs = g_qkvs;

    int n0 = blockIdx.x * NB;
    int dbase = n0 & ~(Tt - 1);
    int lo = n0 - 8; if (lo < dbase) lo = dbase;
    int hi = n0 + NB + 8; if (hi > dbase + Tt) hi = dbase + Tt;
    int nrows = hi - lo;
    int tid = threadIdx.x;

    for (int idx = tid; idx < 128; idx += 256) {
        ((float4*)gm)[idx] = ((const float4*)gamma)[idx];
        ((float4*)bt)[idx] = ((const float4*)beta)[idx];
    }
    for (int idx = tid; idx < nrows * 128; idx += 256) {
        int r = idx >> 7, c = idx & 127;
        const float* row = qkvs + (size_t)(lo + r) * QK;
        ((float4*)ks)[r * 128 + c] = ((const float4*)(row + 512))[c];
        ((float4*)vs)[r * 128 + c] = ((const float4*)(row + 1024))[c];
    }
    __syncthreads();

    int w = tid >> 5, lane = tid & 31;
    const unsigned FULL = 0xffffffffu;
    const float scale = 0.04419417382415922f;   // 1/sqrt(512)

    for (int s = 0; s < 4; s++) {
        int i = n0 + w * 4 + s;
        int elo = 0, nE = 0;
        if (lane == 0) {
            elo = lower_bound_i(dst, E, i);
            int ehi = lower_bound_i(dst, E, i + 1);
            nE = ehi - elo; if (nE > 16) nE = 16;
        }
        elo = __shfl_sync(FULL, elo, 0);
        nE  = __shfl_sync(FULL, nE, 0);

        int sE = 0;
        if (lane < nE) sE = src[elo + lane] - lo;

        float4 q[4];
        const float4* qp = (const float4*)(qkvs + (size_t)i * QK) + lane;
        #pragma unroll
        for (int c = 0; c < 4; c++) q[c] = qp[c * 32];

        // logits: lane e holds logit of edge e
        float lg = -INFINITY;
        for (int e = 0; e < nE; e++) {
            int row = __shfl_sync(FULL, sE, e);
            const float4* kr = (const float4*)(ks + row * Dv) + lane;
            float sum = 0.f;
            #pragma unroll
            for (int c = 0; c < 4; c++) {
                float4 kb = kr[c * 32];
                sum += q[c].x*kb.x + q[c].y*kb.y + q[c].z*kb.z + q[c].w*kb.w;
            }
            #pragma unroll
            for (int o = 16; o; o >>= 1) sum += __shfl_xor_sync(FULL, sum, o);
            if (lane == e) lg = sum * scale;
        }
        float mx = lg;
        #pragma unroll
        for (int o = 16; o; o >>= 1) mx = fmaxf(mx, __shfl_xor_sync(FULL, mx, o));
        if (!isfinite(mx)) mx = 0.f;
        float ex = (lane < nE) ? expf(lg - mx) : 0.f;
        float den = ex;
        #pragma unroll
        for (int o = 16; o; o >>= 1) den += __shfl_xor_sync(FULL, den, o);
        float inv = 1.f / fmaxf(den, 1e-16f);

        float4 acc[4] = {};
        for (int e = 0; e < nE; e++) {
            int row = __shfl_sync(FULL, sE, e);
            float a = __shfl_sync(FULL, ex, e) * inv;
            const float4* vr = (const float4*)(vs + row * Dv) + lane;
            #pragma unroll
            for (int c = 0; c < 4; c++) {
                float4 vv = vr[c * 32];
                acc[c].x += a * vv.x; acc[c].y += a * vv.y;
                acc[c].z += a * vv.z; acc[c].w += a * vv.w;
            }
        }

        const float4* skp = (const float4*)(qkvs + (size_t)i * QK + 1536) + lane;
        const float4* xp  = (const float4*)(x + (size_t)i * Dv) + lane;
        float4 o4[4];
        float s1 = 0.f, s2 = 0.f;
        #pragma unroll
        for (int c = 0; c < 4; c++) {
            float4 sk = skp[c * 32];
            float4 xv = xp[c * 32];
            float h0 = acc[c].x + sk.x, h1 = acc[c].y + sk.y;
            float h2 = acc[c].z + sk.z, h3 = acc[c].w + sk.w;
            h0 = h0 > 0.f ? h0 : 0.01f * h0;
            h1 = h1 > 0.f ? h1 : 0.01f * h1;
            h2 = h2 > 0.f ? h2 : 0.01f * h2;
            h3 = h3 > 0.f ? h3 : 0.01f * h3;
            float o0 = xv.x + h0, o1 = xv.y + h1, o2 = xv.z + h2, o3 = xv.w + h3;
            o4[c].x = o0; o4[c].y = o1; o4[c].z = o2; o4[c].w = o3;
            s1 += o0 + o1 + o2 + o3;
            s2 += o0*o0 + o1*o1 + o2*o2 + o3*o3;
        }
        #pragma unroll
        for (int o = 16; o; o >>= 1) {
            s1 += __shfl_xor_sync(FULL, s1, o);
            s2 += __shfl_xor_sync(FULL, s2, o);
        }
        float mu = s1 / 512.f;
        float var = s2 / 512.f - mu * mu;
        float rs = rsqrtf(var + 1e-5f);

        float4* op = (float4*)(out + (size_t)i * Dv) + lane;
        const float4* gp = (const float4*)gm + lane;
        const float4* bp = (const float4*)bt + lane;
        #pragma unroll
        for (int c = 0; c < 4; c++) {
            float4 gj = gp[c * 32];
            float4 bj = bp[c * 32];
            float4 ov;
            ov.x = (o4[c].x - mu) * rs * gj.x + bj.x;
            ov.y = (o4[c].y - mu) * rs * gj.y + bj.y;
            ov.z = (o4[c].z - mu) * rs * gj.z + bj.z;
            ov.w = (o4[c].w - mu) * rs * gj.w + bj.w;
            op[c * 32] = ov;
        }
    }
}

// scalar loss output (always 0 in eval path)
__global__ void tail_kernel(float* out, int out_size) {
    int idx = Nn * Dv + threadIdx.x;
    if (idx < out_size) out[idx] = 0.f;
}

extern "C" void kernel_launch(void* const* d_in, const int* in_sizes, int n_in,
                              void* d_out, int out_size) {
    const float* x     = (const float*)d_in[0];
    const int*   ei    = (const int*)  d_in[1];
    const int*   et    = (const int*)  d_in[2];
    const float* Wrel  = (const float*)d_in[3];
    const float* Wroot = (const float*)d_in[4];
    const float* brg   = (const float*)d_in[5];
    const float* Wq    = (const float*)d_in[6];
    const float* bq    = (const float*)d_in[7];
    const float* Wk    = (const float*)d_in[8];
    const float* bk    = (const float*)d_in[9];
    const float* Wv    = (const float*)d_in[10];
    const float* bv    = (const float*)d_in[11];
    const float* Wsk   = (const float*)d_in[12];
    const float* bsk   = (const float*)d_in[13];
    const float* gamma = (const float*)d_in[14];
    const float* beta  = (const float*)d_in[15];
    float* out = (float*)d_out;

    int E = in_sizes[2];
    const int* src = ei;
    const int* dst = ei + E;

    cudaFuncSetAttribute(gemm_rgcn, cudaFuncAttributeMaxDynamicSharedMemorySize, GEMM_SMEM_BYTES);
    cudaFuncSetAttribute(gemm_qkvs, cudaFuncAttributeMaxDynamicSharedMemorySize, GEMM_SMEM_BYTES);
    cudaFuncSetAttribute(agg_kernel, cudaFuncAttributeMaxDynamicSharedMemorySize, AGG_SMEM);
    cudaFuncSetAttribute(attn_kernel, cudaFuncAttributeMaxDynamicSharedMemorySize, ATT_SMEM);

    pack_weights<<<K1 / 2 + 4 * (Dv / 2), 512>>>(Wrel, Wroot, Wq, Wk, Wv, Wsk);
    agg_kernel<<<Nn / NB, 256, AGG_SMEM>>>(x, src, dst, et, E);
    gemm_rgcn<<<dim3(Dv / 128, Nn / 128), 256, GEMM_SMEM_BYTES>>>(brg);
    gemm_qkvs<<<dim3(QK / 128, Nn / 128), 256, GEMM_SMEM_BYTES>>>(bq, bk, bv, bsk);
    attn_kernel<<<Nn / NB, 256, ATT_SMEM>>>(x, src, dst, E, gamma, beta, out);
    if (out_size > Nn * Dv) tail_kernel<<<1, 256>>>(out, out_size);
}

// round 17
// speedup vs baseline: 1.4545x; 1.1697x over previous
#include <cuda_runtime.h>
#include <cuda_bf16.h>
#include <math.h>
#include <stdint.h>

#define Dv   512
#define Nn   8192
#define K1   2560    // 5*D  (Agg_0..3, x)
#define QK   2048    // 4*D  (q,k,v,skip)

// ---- static scratch (no allocations allowed) ----
__device__ __nv_bfloat16 g_H0[(size_t)Nn * K1];   // 40 MB  [N, 5D] bf16
__device__ __nv_bfloat16 g_ho[(size_t)Nn * Dv];   //  8 MB  [N, D]  bf16
__device__ float         g_qkvs[(size_t)Nn * QK]; // 64 MB  [N, 4, D] fp32
__device__ uint32_t      g_Wp1n[(size_t)Dv * (K1 / 2)];   // 2.6 MB n-major packed [W_rel;W_root]
__device__ uint32_t      g_Wp2n[(size_t)QK * (Dv / 2)];   // 2.0 MB n-major packed q|k|v|skip

__device__ __forceinline__ int lower_bound_i(const int* __restrict__ a, int n, int key) {
    int lo = 0, hi = n;
    while (lo < hi) { int m = (lo + hi) >> 1; if (a[m] < key) lo = m + 1; else hi = m; }
    return lo;
}

__device__ __forceinline__ uint32_t packbf(float lo, float hi) {
    __nv_bfloat162 h = __floats2bfloat162_rn(lo, hi);   // x (low) = lo
    return reinterpret_cast<uint32_t&>(h);
}

__device__ __forceinline__ uint2 f4_to_bf(float4 v) {
    uint2 r; r.x = packbf(v.x, v.y); r.y = packbf(v.z, v.w); return r;
}

// m16n8k16 bf16 mma, fp32 accum
__device__ __forceinline__ void mma16(float* d, const uint32_t* a, const uint32_t* b) {
    asm volatile(
        "mma.sync.aligned.m16n8k16.row.col.f32.bf16.bf16.f32 "
        "{%0,%1,%2,%3}, {%4,%5,%6,%7}, {%8,%9}, {%0,%1,%2,%3};"
        : "+f"(d[0]), "+f"(d[1]), "+f"(d[2]), "+f"(d[3])
        : "r"(a[0]), "r"(a[1]), "r"(a[2]), "r"(a[3]), "r"(b[0]), "r"(b[1]));
}

__device__ __forceinline__ void ldsm_x4(uint32_t* r, uint32_t addr) {
    asm volatile("ldmatrix.sync.aligned.m8n8.x4.shared.b16 {%0,%1,%2,%3}, [%4];"
        : "=r"(r[0]), "=r"(r[1]), "=r"(r[2]), "=r"(r[3]) : "r"(addr));
}
__device__ __forceinline__ void ldsm_x2(uint32_t* r, uint32_t addr) {
    asm volatile("ldmatrix.sync.aligned.m8n8.x2.shared.b16 {%0,%1}, [%2];"
        : "=r"(r[0]), "=r"(r[1]) : "r"(addr));
}

__device__ __forceinline__ void cpa16(void* smem, const void* g) {
    uint32_t s = (uint32_t)__cvta_generic_to_shared(smem);
    asm volatile("cp.async.ca.shared.global [%0], [%1], 16;" :: "r"(s), "l"(g));
}
#define CP_COMMIT() asm volatile("cp.async.commit_group;")
#define CP_WAIT2()  asm volatile("cp.async.wait_group 2;")

// ============================================================
// Kernel 0a/0b: transpose-pack weights -> n-major bf16 pairs
// Wp1n[n][kp] = pack(W1[2kp][n], W1[2kp+1][n]),  W1 = [Wrel;Wroot]
// ============================================================
__global__ __launch_bounds__(256) void tp_w1(
    const float* __restrict__ Wrel, const float* __restrict__ Wroot)
{
    __shared__ float tile[32][33];
    int k0 = blockIdx.x * 32, n0 = blockIdx.y * 32;
    int tx = threadIdx.x, ty = threadIdx.y;   // (32, 8)
    #pragma unroll
    for (int i = 0; i < 4; i++) {
        int k = k0 + ty * 4 + i;
        const float* srcp = (k < 2048) ? (Wrel + (size_t)k * Dv) : (Wroot + (size_t)(k - 2048) * Dv);
        tile[ty * 4 + i][tx] = srcp[n0 + tx];
    }
    __syncthreads();
    if (tx < 16) {
        #pragma unroll
        for (int i = 0; i < 4; i++) {
            int r = ty * 4 + i;   // n within tile
            g_Wp1n[(size_t)(n0 + r) * (K1 / 2) + k0 / 2 + tx] =
                packbf(tile[2 * tx][r], tile[2 * tx + 1][r]);
        }
    }
}

__global__ __launch_bounds__(256) void tp_w2(
    const float* __restrict__ Wq, const float* __restrict__ Wk,
    const float* __restrict__ Wv, const float* __restrict__ Ws)
{
    __shared__ float tile[32][33];
    int k0 = blockIdx.x * 32, r0 = blockIdx.y * 32;  // r0 = global n' in [0,2048)
    int w = r0 >> 9, nloc = r0 & 511;
    const float* W = (w == 0) ? Wq : (w == 1) ? Wk : (w == 2) ? Wv : Ws;
    int tx = threadIdx.x, ty = threadIdx.y;
    #pragma unroll
    for (int i = 0; i < 4; i++)
        tile[ty * 4 + i][tx] = W[(size_t)(k0 + ty * 4 + i) * Dv + nloc + tx];
    __syncthreads();
    if (tx < 16) {
        #pragma unroll
        for (int i = 0; i < 4; i++) {
            int r = ty * 4 + i;
            g_Wp2n[(size_t)(r0 + r) * (Dv / 2) + k0 / 2 + tx] =
                packbf(tile[2 * tx][r], tile[2 * tx + 1][r]);
        }
    }
}

// ============================================================
// Kernel 1: per-node per-relation neighbor mean -> H0 [N, 5D] (bf16)
// (R12-proven version)
// ============================================================
__global__ __launch_bounds__(128) void agg_kernel(
    const float* __restrict__ x,
    const int*   __restrict__ src,
    const int*   __restrict__ dst,
    const int*   __restrict__ et,
    int E)
{
    int i = blockIdx.x;
    int t = threadIdx.x;
    __shared__ int s_lo, s_nE;
    __shared__ int s_src[32], s_rel[32];
    __shared__ int s_cnt[4];

    if (t == 0) {
        int lo = lower_bound_i(dst, E, i);
        int hi = lower_bound_i(dst, E, i + 1);
        s_lo = lo;
        int n = hi - lo; if (n > 32) n = 32;
        s_nE = n;
    }
    if (t < 4) s_cnt[t] = 0;
    __syncthreads();
    int nE = s_nE, lo = s_lo;
    if (t < nE) {
        s_src[t] = src[lo + t];
        int r = et[lo + t];
        s_rel[t] = r;
        atomicAdd(&s_cnt[r], 1);
    }
    __syncthreads();

    int d0 = t * 4;
    float4 a0 = {0,0,0,0}, a1 = a0, a2 = a0, a3 = a0;
    for (int e = 0; e < nE; e++) {
        int s = s_src[e];
        float4 v = *reinterpret_cast<const float4*>(x + (size_t)s * Dv + d0);
        int r = s_rel[e];
        if (r == 0)      { a0.x += v.x; a0.y += v.y; a0.z += v.z; a0.w += v.w; }
        else if (r == 1) { a1.x += v.x; a1.y += v.y; a1.z += v.z; a1.w += v.w; }
        else if (r == 2) { a2.x += v.x; a2.y += v.y; a2.z += v.z; a2.w += v.w; }
        else             { a3.x += v.x; a3.y += v.y; a3.z += v.z; a3.w += v.w; }
    }
    float i0 = 1.f / fmaxf((float)s_cnt[0], 1.f);
    float i1 = 1.f / fmaxf((float)s_cnt[1], 1.f);
    float i2 = 1.f / fmaxf((float)s_cnt[2], 1.f);
    float i3 = 1.f / fmaxf((float)s_cnt[3], 1.f);
    a0.x*=i0; a0.y*=i0; a0.z*=i0; a0.w*=i0;
    a1.x*=i1; a1.y*=i1; a1.z*=i1; a1.w*=i1;
    a2.x*=i2; a2.y*=i2; a2.z*=i2; a2.w*=i2;
    a3.x*=i3; a3.y*=i3; a3.z*=i3; a3.w*=i3;
    __nv_bfloat16* H = g_H0 + (size_t)i * K1;
    *reinterpret_cast<uint2*>(H + 0*Dv + d0) = f4_to_bf(a0);
    *reinterpret_cast<uint2*>(H + 1*Dv + d0) = f4_to_bf(a1);
    *reinterpret_cast<uint2*>(H + 2*Dv + d0) = f4_to_bf(a2);
    *reinterpret_cast<uint2*>(H + 3*Dv + d0) = f4_to_bf(a3);
    float4 xv = *reinterpret_cast<const float4*>(x + (size_t)i * Dv + d0);
    *reinterpret_cast<uint2*>(H + 4*Dv + d0) = f4_to_bf(xv);
}

// ============================================================
// bf16 GEMM: 128x128x32 tiles, 8 warps (2x4), warp tile 64x32,
// 4-stage cp.async ring (wait_group 2), ldmatrix fragment loads.
// As: [m][k/2] uint32, lead 20.  Bsn: [n][k/2] uint32, lead 20.
// ============================================================
#define LDA32 20
#define LDBN  20
#define AS_ST (128 * LDA32)    // 2560 words
#define BS_ST (128 * LDBN)     // 2560 words
#define NSTAGE 4
#define GEMM_SMEM_BYTES ((AS_ST + BS_ST) * NSTAGE * 4)   // 81920

__global__ __launch_bounds__(256) void gemm_rgcn(const float* __restrict__ bias)
{
    extern __shared__ uint32_t smem[];
    uint32_t* As = smem;
    uint32_t* Bs = smem + NSTAGE * AS_ST;
    const __nv_bfloat16* A = g_H0;
    const uint32_t* Wpn = g_Wp1n;           // [512][1280]
    const int ROWLEN = K1 / 2;
    __nv_bfloat16* C = g_ho;
    const int K = K1;
    int tid = threadIdx.x;
    int n0 = blockIdx.x * 128, m0 = blockIdx.y * 128;
    int wid = tid >> 5, lane = tid & 31;
    int wr = wid >> 2, wc = wid & 3;
    int g = lane >> 2, tig = lane & 3;
    float acc[4][4][4] = {};

    int a_row0 = tid >> 2,            a_kw0 = (tid & 3) * 4;
    int a_row1 = (tid + 256) >> 2,    a_kw1 = a_kw0;
    int b_row0 = a_row0,              b_kw0 = a_kw0;
    int b_row1 = a_row1,              b_kw1 = a_kw0;

    // per-lane ldmatrix byte offsets
    int a_lm = ((lane & 15) * LDA32 + (lane >> 4) * 4) * 4;
    int b_lm = ((lane & 7) * LDBN + ((lane >> 3) & 1) * 4) * 4;

    const int ITER = K / 32;   // 80
    #pragma unroll
    for (int s = 0; s < NSTAGE - 1; s++) {
        int kb = s * 32, kpb = s * 16;
        cpa16(&As[s*AS_ST + a_row0 * LDA32 + a_kw0], A + (size_t)(m0 + a_row0) * K + kb + a_kw0 * 2);
        cpa16(&As[s*AS_ST + a_row1 * LDA32 + a_kw1], A + (size_t)(m0 + a_row1) * K + kb + a_kw1 * 2);
        cpa16(&Bs[s*BS_ST + b_row0 * LDBN + b_kw0], Wpn + (size_t)(n0 + b_row0) * ROWLEN + kpb + b_kw0);
        cpa16(&Bs[s*BS_ST + b_row1 * LDBN + b_kw1], Wpn + (size_t)(n0 + b_row1) * ROWLEN + kpb + b_kw1);
        CP_COMMIT();
    }
    for (int it = 0; it < ITER; ++it) {
        CP_WAIT2();
        __syncthreads();
        if (it + NSTAGE - 1 < ITER) {
            int st = (it + NSTAGE - 1) & (NSTAGE - 1);
            int kb = (it + NSTAGE - 1) * 32;
            int kpb = (it + NSTAGE - 1) * 16;
            cpa16(&As[st*AS_ST + a_row0 * LDA32 + a_kw0], A + (size_t)(m0 + a_row0) * K + kb + a_kw0 * 2);
            cpa16(&As[st*AS_ST + a_row1 * LDA32 + a_kw1], A + (size_t)(m0 + a_row1) * K + kb + a_kw1 * 2);
            cpa16(&Bs[st*BS_ST + b_row0 * LDBN + b_kw0], Wpn + (size_t)(n0 + b_row0) * ROWLEN + kpb + b_kw0);
            cpa16(&Bs[st*BS_ST + b_row1 * LDBN + b_kw1], Wpn + (size_t)(n0 + b_row1) * ROWLEN + kpb + b_kw1);
        }
        CP_COMMIT();
        uint32_t asb = (uint32_t)__cvta_generic_to_shared(&As[(it & (NSTAGE - 1)) * AS_ST]);
        uint32_t bsb = (uint32_t)__cvta_generic_to_shared(&Bs[(it & (NSTAGE - 1)) * BS_ST]);
        #pragma unroll
        for (int ks = 0; ks < 2; ks++) {
            uint32_t af[4][4], bf[4][2];
            #pragma unroll
            for (int mt = 0; mt < 4; mt++)
                ldsm_x4(af[mt], asb + ((wr * 64 + mt * 16) * LDA32 + ks * 8) * 4 + a_lm);
            #pragma unroll
            for (int nt = 0; nt < 4; nt++)
                ldsm_x2(bf[nt], bsb + ((wc * 32 + nt * 8) * LDBN + ks * 8) * 4 + b_lm);
            #pragma unroll
            for (int mt = 0; mt < 4; mt++)
                #pragma unroll
                for (int nt = 0; nt < 4; nt++)
                    mma16(acc[mt][nt], af[mt], bf[nt]);
        }
    }
    #pragma unroll
    for (int mt = 0; mt < 4; mt++) {
        int mr = m0 + wr * 64 + mt * 16;
        #pragma unroll
        for (int nt = 0; nt < 4; nt++) {
            int nc = n0 + wc * 32 + nt * 8 + 2 * tig;
            float b0 = bias[nc], b1 = bias[nc + 1];
            uint32_t v0 = packbf(acc[mt][nt][0] + b0, acc[mt][nt][1] + b1);
            uint32_t v1 = packbf(acc[mt][nt][2] + b0, acc[mt][nt][3] + b1);
            *(uint32_t*)(C + (size_t)(mr + g)     * Dv + nc) = v0;
            *(uint32_t*)(C + (size_t)(mr + g + 8) * Dv + nc) = v1;
        }
    }
}

__global__ __launch_bounds__(256) void gemm_qkvs(
    const float* __restrict__ bq, const float* __restrict__ bk,
    const float* __restrict__ bv, const float* __restrict__ bs_)
{
    extern __shared__ uint32_t smem[];
    uint32_t* As = smem;
    uint32_t* Bs = smem + NSTAGE * AS_ST;
    const __nv_bfloat16* A = g_ho;
    const uint32_t* Wpn = g_Wp2n;           // [2048][256]
    const int ROWLEN = Dv / 2;
    float* C = g_qkvs;
    const int K = Dv;
    int tid = threadIdx.x;
    int n0 = blockIdx.x * 128, m0 = blockIdx.y * 128;
    int wsel = n0 >> 9;
    const float* bb = (wsel == 0) ? bq : (wsel == 1) ? bk : (wsel == 2) ? bv : bs_;
    int bc0 = n0 & 511;
    int wid = tid >> 5, lane = tid & 31;
    int wr = wid >> 2, wc = wid & 3;
    int g = lane >> 2, tig = lane & 3;
    float acc[4][4][4] = {};

    int a_row0 = tid >> 2,            a_kw0 = (tid & 3) * 4;
    int a_row1 = (tid + 256) >> 2,    a_kw1 = a_kw0;
    int b_row0 = a_row0,              b_kw0 = a_kw0;
    int b_row1 = a_row1,              b_kw1 = a_kw0;

    int a_lm = ((lane & 15) * LDA32 + (lane >> 4) * 4) * 4;
    int b_lm = ((lane & 7) * LDBN + ((lane >> 3) & 1) * 4) * 4;

    const int ITER = K / 32;   // 16
    #pragma unroll
    for (int s = 0; s < NSTAGE - 1; s++) {
        int kb = s * 32, kpb = s * 16;
        cpa16(&As[s*AS_ST + a_row0 * LDA32 + a_kw0], A + (size_t)(m0 + a_row0) * K + kb + a_kw0 * 2);
        cpa16(&As[s*AS_ST + a_row1 * LDA32 + a_kw1], A + (size_t)(m0 + a_row1) * K + kb + a_kw1 * 2);
        cpa16(&Bs[s*BS_ST + b_row0 * LDBN + b_kw0], Wpn + (size_t)(n0 + b_row0) * ROWLEN + kpb + b_kw0);
        cpa16(&Bs[s*BS_ST + b_row1 * LDBN + b_kw1], Wpn + (size_t)(n0 + b_row1) * ROWLEN + kpb + b_kw1);
        CP_COMMIT();
    }
    for (int it = 0; it < ITER; ++it) {
        CP_WAIT2();
        __syncthreads();
        if (it + NSTAGE - 1 < ITER) {
            int st = (it + NSTAGE - 1) & (NSTAGE - 1);
            int kb = (it + NSTAGE - 1) * 32;
            int kpb = (it + NSTAGE - 1) * 16;
            cpa16(&As[st*AS_ST + a_row0 * LDA32 + a_kw0], A + (size_t)(m0 + a_row0) * K + kb + a_kw0 * 2);
            cpa16(&As[st*AS_ST + a_row1 * LDA32 + a_kw1], A + (size_t)(m0 + a_row1) * K + kb + a_kw1 * 2);
            cpa16(&Bs[st*BS_ST + b_row0 * LDBN + b_kw0], Wpn + (size_t)(n0 + b_row0) * ROWLEN + kpb + b_kw0);
            cpa16(&Bs[st*BS_ST + b_row1 * LDBN + b_kw1], Wpn + (size_t)(n0 + b_row1) * ROWLEN + kpb + b_kw1);
        }
        CP_COMMIT();
        uint32_t asb = (uint32_t)__cvta_generic_to_shared(&As[(it & (NSTAGE - 1)) * AS_ST]);
        uint32_t bsb = (uint32_t)__cvta_generic_to_shared(&Bs[(it & (NSTAGE - 1)) * BS_ST]);
        #pragma unroll
        for (int ks = 0; ks < 2; ks++) {
            uint32_t af[4][4], bf[4][2];
            #pragma unroll
            for (int mt = 0; mt < 4; mt++)
                ldsm_x4(af[mt], asb + ((wr * 64 + mt * 16) * LDA32 + ks * 8) * 4 + a_lm);
            #pragma unroll
            for (int nt = 0; nt < 4; nt++)
                ldsm_x2(bf[nt], bsb + ((wc * 32 + nt * 8) * LDBN + ks * 8) * 4 + b_lm);
            #pragma unroll
            for (int mt = 0; mt < 4; mt++)
                #pragma unroll
                for (int nt = 0; nt < 4; nt++)
                    mma16(acc[mt][nt], af[mt], bf[nt]);
        }
    }
    #pragma unroll
    for (int mt = 0; mt < 4; mt++) {
        int mr = m0 + wr * 64 + mt * 16;
        #pragma unroll
        for (int nt = 0; nt < 4; nt++) {
            int colw = wc * 32 + nt * 8 + 2 * tig;
            int nc = n0 + colw;
            int bi = bc0 + colw;
            float b0 = bb[bi], b1 = bb[bi + 1];
            float2 v0 = {acc[mt][nt][0] + b0, acc[mt][nt][1] + b1};
            float2 v1 = {acc[mt][nt][2] + b0, acc[mt][nt][3] + b1};
            *(float2*)(C + (size_t)(mr + g)     * QK + nc) = v0;
            *(float2*)(C + (size_t)(mr + g + 8) * QK + nc) = v1;
        }
    }
}

// ============================================================
// Kernel 4: attention softmax + skip + leaky + residual + LN
// (R12-proven version: 128 threads/block, one block per node)
// ============================================================
__global__ __launch_bounds__(128) void attn_kernel(
    const float* __restrict__ x,
    const int*   __restrict__ src,
    const int*   __restrict__ dst,
    int E,
    const float* __restrict__ gamma,
    const float* __restrict__ beta,
    float* __restrict__ out)
{
    int i = blockIdx.x;
    int t = threadIdx.x;     // 0..127
    __shared__ float q_s[512];
    __shared__ float logit[32];
    __shared__ float alpha_s[32];
    __shared__ int   s_src[32];
    __shared__ int   s_lo, s_nE;
    __shared__ float red1[4], red2[4];
    __shared__ float s_mu, s_rstd;
    const float* qkvs = g_qkvs;

    if (t == 0) {
        int lo = lower_bound_i(dst, E, i);
        int hi = lower_bound_i(dst, E, i + 1);
        s_lo = lo; int n = hi - lo; if (n > 32) n = 32; s_nE = n;
    }
    __syncthreads();
    int nE = s_nE, lo = s_lo;
    int d0 = t * 4;
    *(float4*)&q_s[d0] = *(const float4*)(qkvs + (size_t)i * QK + d0);
    if (t < nE) s_src[t] = src[lo + t];
    __syncthreads();

    int wid = t >> 5, lane = t & 31;
    for (int e = wid; e < nE; e += 4) {
        const float* kp = qkvs + (size_t)s_src[e] * QK + 512;
        float sum = 0.f;
        #pragma unroll
        for (int c = 0; c < 4; c++) {
            int d = c * 128 + lane * 4;
            float4 qa = *(const float4*)&q_s[d];
            float4 kb = *(const float4*)(kp + d);
            sum += qa.x*kb.x + qa.y*kb.y + qa.z*kb.z + qa.w*kb.w;
        }
        #pragma unroll
        for (int o = 16; o; o >>= 1) sum += __shfl_xor_sync(0xffffffffu, sum, o);
        if (lane == 0) logit[e] = sum * 0.04419417382415922f; // 1/sqrt(512)
    }
    __syncthreads();
    if (wid == 0) {
        float l = (lane < nE) ? logit[lane] : -INFINITY;
        float mx = l;
        #pragma unroll
        for (int o = 16; o; o >>= 1) mx = fmaxf(mx, __shfl_xor_sync(0xffffffffu, mx, o));
        if (!isfinite(mx)) mx = 0.f;
        float ex = (lane < nE) ? expf(l - mx) : 0.f;
        float den = ex;
        #pragma unroll
        for (int o = 16; o; o >>= 1) den += __shfl_xor_sync(0xffffffffu, den, o);
        float inv = 1.f / fmaxf(den, 1e-16f);
        alpha_s[lane] = ex * inv;
    }
    __syncthreads();

    float4 accv = {0,0,0,0};
    for (int e = 0; e < nE; e++) {
        float a = alpha_s[e];
        float4 v = *(const float4*)(qkvs + (size_t)s_src[e] * QK + 1024 + d0);
        accv.x += a * v.x; accv.y += a * v.y; accv.z += a * v.z; accv.w += a * v.w;
    }
    float4 sk = *(const float4*)(qkvs + (size_t)i * QK + 1536 + d0);
    float h0 = accv.x + sk.x, h1 = accv.y + sk.y;
    float h2 = accv.z + sk.z, h3 = accv.w + sk.w;
    h0 = h0 > 0.f ? h0 : 0.01f * h0;
    h1 = h1 > 0.f ? h1 : 0.01f * h1;
    h2 = h2 > 0.f ? h2 : 0.01f * h2;
    h3 = h3 > 0.f ? h3 : 0.01f * h3;
    float4 xv = *(const float4*)(x + (size_t)i * Dv + d0);
    float o0 = xv.x + h0, o1 = xv.y + h1, o2 = xv.z + h2, o3 = xv.w + h3;

    float s1 = o0 + o1 + o2 + o3;
    float s2 = o0*o0 + o1*o1 + o2*o2 + o3*o3;
    #pragma unroll
    for (int o = 16; o; o >>= 1) {
        s1 += __shfl_xor_sync(0xffffffffu, s1, o);
        s2 += __shfl_xor_sync(0xffffffffu, s2, o);
    }
    if (lane == 0) { red1[wid] = s1; red2[wid] = s2; }
    __syncthreads();
    if (t == 0) {
        float S1 = red1[0] + red1[1] + red1[2] + red1[3];
        float S2 = red2[0] + red2[1] + red2[2] + red2[3];
        float mu = S1 / 512.f;
        float var = S2 / 512.f - mu * mu;
        s_mu = mu; s_rstd = rsqrtf(var + 1e-5f);
    }
    __syncthreads();
    float mu = s_mu, rs = s_rstd;
    float4 gm = *(const float4*)(gamma + d0);
    float4 bt = *(const float4*)(beta + d0);
    float4 ov;
    ov.x = (o0 - mu) * rs * gm.x + bt.x;
    ov.y = (o1 - mu) * rs * gm.y + bt.y;
    ov.z = (o2 - mu) * rs * gm.z + bt.z;
    ov.w = (o3 - mu) * rs * gm.w + bt.w;
    *(float4*)(out + (size_t)i * Dv + d0) = ov;
}

// scalar loss output (always 0 in eval path)
__global__ void tail_kernel(float* out, int out_size) {
    int idx = Nn * Dv + threadIdx.x;
    if (idx < out_size) out[idx] = 0.f;
}

extern "C" void kernel_launch(void* const* d_in, const int* in_sizes, int n_in,
                              void* d_out, int out_size) {
    const float* x     = (const float*)d_in[0];
    const int*   ei    = (const int*)  d_in[1];
    const int*   et    = (const int*)  d_in[2];
    const float* Wrel  = (const float*)d_in[3];
    const float* Wroot = (const float*)d_in[4];
    const float* brg   = (const float*)d_in[5];
    const float* Wq    = (const float*)d_in[6];
    const float* bq    = (const float*)d_in[7];
    const float* Wk    = (const float*)d_in[8];
    const float* bk    = (const float*)d_in[9];
    const float* Wv    = (const float*)d_in[10];
    const float* bv    = (const float*)d_in[11];
    const float* Wsk   = (const float*)d_in[12];
    const float* bsk   = (const float*)d_in[13];
    const float* gamma = (const float*)d_in[14];
    const float* beta  = (const float*)d_in[15];
    float* out = (float*)d_out;

    int E = in_sizes[2];
    const int* src = ei;
    const int* dst = ei + E;

    cudaFuncSetAttribute(gemm_rgcn, cudaFuncAttributeMaxDynamicSharedMemorySize, GEMM_SMEM_BYTES);
    cudaFuncSetAttribute(gemm_qkvs, cudaFuncAttributeMaxDynamicSharedMemorySize, GEMM_SMEM_BYTES);

    tp_w1<<<dim3(K1 / 32, Dv / 32), dim3(32, 8)>>>(Wrel, Wroot);
    tp_w2<<<dim3(Dv / 32, QK / 32), dim3(32, 8)>>>(Wq, Wk, Wv, Wsk);
    agg_kernel<<<Nn, 128>>>(x, src, dst, et, E);
    gemm_rgcn<<<dim3(Dv / 128, Nn / 128), 256, GEMM_SMEM_BYTES>>>(brg);
    gemm_qkvs<<<dim3(QK / 128, Nn / 128), 256, GEMM_SMEM_BYTES>>>(bq, bk, bv, bsk);
    attn_kernel<<<Nn, 128>>>(x, src, dst, E, gamma, beta, out);
    if (out_size > Nn * Dv) tail_kernel<<<1, 256>>>(out, out_size);
}